// round 3
// baseline (speedup 1.0000x reference)
#include <cuda_runtime.h>
#include <math.h>

// ---------------------------------------------------------------------------
// DifferentiableModalPlate: disp[t] = sum_m P_m * exp(-sigma_m*(t-1)*K)
//                                          * sin((t*omega_m)*K)/den_m,
// then normalized by max|disp|+1e-8.
// Strategy: replicate the reference's fp32 rounding order exactly in the hot
// arguments ((t*omega)*K and ((-sigma)*(t-1))*K) and use accurate sinf/expf.
// Per-mode prep uses explicit round-to-nearest intrinsics (no FMA contraction)
// to mirror XLA CPU's unfused elementwise ops.
// ---------------------------------------------------------------------------

#define TPB     256
#define NCHUNK  10
#define CHUNK   640      // NCHUNK * CHUNK == MODES
#define MODES   6400
#define MMAXI   80
#define MAXT    32768

__device__ float4 g_modes[MODES];          // {omega, -sigma, coef=P/den, 0}
__device__ float  g_part[NCHUNK][MAXT];    // per-chunk partial time series
__device__ float  g_disp[MAXT];            // combined (unnormalized) output
__device__ float  g_peak;                  // max |disp|

__device__ __forceinline__ float softplus_ref(float x) {
    // jax.nn.softplus = logaddexp(x, 0) = max(x,0) + log1p(exp(-|x|))
    return fmaxf(x, 0.0f) + log1pf(expf(-fabsf(x)));
}

__device__ __forceinline__ float sigmoid_ref(float x) {
    if (x >= 0.0f) { float e = expf(-x); return 1.0f / (1.0f + e); }
    float e = expf(x); return e / (1.0f + e);
}

// ---------------- per-mode parameter precompute (6400 lanes) ----------------
__global__ void plate_prep_kernel(const float* mu_raw, const float* Dmu_raw,
                                  const float* T0mu_raw, const float* Ly_raw,
                                  const float* xo_raw, const float* yo_raw)
{
    const float K_F   = (float)(1.0 / 44100.0);
    const float KK_F  = (float)((1.0 / 44100.0) * (1.0 / 44100.0)); // K*K in double, rounded once
    const float PI_F  = (float)M_PI;
    const float XIPI  = (float)((0.1 * 0.5) * M_PI);   // xi*pi computed in python double
    const float MAXOM = (float)(10000.0 * 2.0 * M_PI);
    const float MINOM = (float)(20.0 * 2.0 * M_PI);
    const double OM2SQ_D = (2.0 * M_PI * 500.0) * (2.0 * M_PI * 500.0);
    const float ALPHA_F = (float)(3.0 * log(10.0) / OM2SQ_D * (OM2SQ_D / 6.0));
    const float BETA_F  = (float)(3.0 * log(10.0) / OM2SQ_D * (1.0 / 1.0 - 1.0 / 6.0));

    // scalar parameter bounds (every thread recomputes; trivial cost)
    float mu  = __fmul_rn(__fadd_rn(softplus_ref(*mu_raw),   1e-4f), 2.43f);
    float Dm  = __fmul_rn(__fadd_rn(softplus_ref(*Dmu_raw),  1e-4f), 0.002452f);
    float T0m = __fmul_rn(__fadd_rn(softplus_ref(*T0mu_raw), 1e-4f), 0.004115f);
    float Ly  = __fadd_rn(1.1f, __fmul_rn((float)(4.0 - 1.1), sigmoid_ref(*Ly_raw)));
    float xo  = __fadd_rn((float)(0.49 * 0.5),
                          __fmul_rn((float)((1.0 - 0.49) * 0.5), sigmoid_ref(*xo_raw)));
    float yo  = __fadd_rn(__fmul_rn(0.51f, Ly),
                          __fmul_rn(__fmul_rn((float)(1.0 - 0.51), Ly), sigmoid_ref(*yo_raw)));
    float yi  = __fmul_rn(0.1f, Ly);
    float ms  = __fmul_rn(__fmul_rn(__fmul_rn(0.25f, mu), 0.5f), Ly);

    for (int i = threadIdx.x; i < MODES; i += blockDim.x) {
        float mf = (float)(i / MMAXI + 1);
        float nf = (float)(i % MMAXI + 1);
        // g1 = (m*pi/LX)^2 + (n*pi/Ly)^2
        float a = __fdiv_rn(__fmul_rn(mf, PI_F), 0.5f);
        float b = __fdiv_rn(__fmul_rn(nf, PI_F), Ly);
        float g1 = __fadd_rn(__fmul_rn(a, a), __fmul_rn(b, b));
        float osq = __fadd_rn(__fmul_rn(T0m, g1), __fmul_rn(__fmul_rn(Dm, g1), g1));
        float omega = sqrtf(fmaxf(osq, 0.0f));
        float valid = (omega <= MAXOM && omega >= MINOM) ? 1.0f : 0.0f;

        float InW = __fmul_rn(
            cosf(__fdiv_rn(__fmul_rn(XIPI, mf), 0.5f)),
            cosf(__fdiv_rn(__fmul_rn(__fmul_rn(yi, PI_F), nf), Ly)));
        float OutW = __fmul_rn(
            cosf(__fdiv_rn(__fmul_rn(__fmul_rn(xo, PI_F), mf), 0.5f)),
            cosf(__fdiv_rn(__fmul_rn(__fmul_rn(yo, PI_F), nf), Ly)));

        float sigma = __fadd_rn(ALPHA_F, __fmul_rn(BETA_F, __fmul_rn(omega, omega)));
        float e0 = expf(__fmul_rn(-sigma, K_F));
        // P = OutW*InW*(K*K)*exp(-sigma*K)/ms * valid   (left-assoc, as in ref)
        float P = __fmul_rn(
            __fdiv_rn(__fmul_rn(__fmul_rn(__fmul_rn(OutW, InW), KK_F), e0), ms), valid);
        float den = __fadd_rn(sinf(__fmul_rn(omega, K_F)), 1e-8f);
        float coef = __fdiv_rn(P, den);

        g_modes[i] = make_float4(omega, -sigma, coef, 0.0f);
    }
}

// ---------------- main synthesis: 141M sin/exp evaluations ------------------
__global__ void plate_synth_kernel(int T)
{
    const float K_F = (float)(1.0 / 44100.0);
    __shared__ float4 sm[CHUNK];
    int base = blockIdx.y * CHUNK;
    for (int j = threadIdx.x; j < CHUNK; j += TPB)
        sm[j] = g_modes[base + j];
    __syncthreads();

    int t = blockIdx.x * TPB + threadIdx.x;
    float tf  = (float)t;
    float tm1 = tf - 1.0f;           // exact
    float acc = 0.0f;

    #pragma unroll 4
    for (int j = 0; j < CHUNK; ++j) {
        float4 md = sm[j];
        // match reference rounding: ph = rnd(rnd(t*omega)*K); ea = rnd(rnd(-sigma*(t-1))*K)
        float ph = __fmul_rn(__fmul_rn(tf, md.x), K_F);
        float ea = __fmul_rn(__fmul_rn(md.y, tm1), K_F);
        acc += md.z * (expf(ea) * sinf(ph));
    }
    if (t < T) g_part[blockIdx.y][t] = acc;
}

// ---------------- fixed-order combine (deterministic, no atomics) -----------
__global__ void plate_combine_kernel(int T)
{
    int t = blockIdx.x * TPB + threadIdx.x;
    if (t < T) {
        float s = 0.0f;
        #pragma unroll
        for (int c = 0; c < NCHUNK; ++c) s += g_part[c][t];
        g_disp[t] = s;
    }
}

// ---------------- peak reduction (single block) ------------------------------
__global__ void plate_peak_kernel(int T)
{
    __shared__ float sh[TPB];
    float m = 0.0f;
    for (int i = threadIdx.x; i < T; i += TPB)
        m = fmaxf(m, fabsf(g_disp[i]));
    sh[threadIdx.x] = m;
    __syncthreads();
    for (int s = TPB / 2; s > 0; s >>= 1) {
        if (threadIdx.x < s)
            sh[threadIdx.x] = fmaxf(sh[threadIdx.x], sh[threadIdx.x + s]);
        __syncthreads();
    }
    if (threadIdx.x == 0) g_peak = sh[0];
}

// ---------------- normalize ---------------------------------------------------
__global__ void plate_norm_kernel(float* __restrict__ out, int T)
{
    int t = blockIdx.x * TPB + threadIdx.x;
    if (t < T)
        out[t] = __fdiv_rn(g_disp[t], __fadd_rn(g_peak, 1e-8f));
}

// ---------------------------------------------------------------------------
extern "C" void kernel_launch(void* const* d_in, const int* in_sizes, int n_in,
                              void* d_out, int out_size)
{
    const float* mu_raw   = (const float*)d_in[0];
    const float* Dmu_raw  = (const float*)d_in[1];
    const float* T0mu_raw = (const float*)d_in[2];
    const float* Ly_raw   = (const float*)d_in[3];
    const float* xo_raw   = (const float*)d_in[4];
    const float* yo_raw   = (const float*)d_in[5];
    float* out = (float*)d_out;

    int T = out_size;
    if (T > MAXT) T = MAXT;
    int tblocks = (T + TPB - 1) / TPB;

    plate_prep_kernel<<<1, TPB>>>(mu_raw, Dmu_raw, T0mu_raw, Ly_raw, xo_raw, yo_raw);

    dim3 grid(tblocks, NCHUNK);
    plate_synth_kernel<<<grid, TPB>>>(T);

    plate_combine_kernel<<<tblocks, TPB>>>(T);
    plate_peak_kernel<<<1, TPB>>>(T);
    plate_norm_kernel<<<tblocks, TPB>>>(out, T);
}

// round 4
// speedup vs baseline: 3.4510x; 3.4510x over previous
#include <cuda_runtime.h>
#include <math.h>

// ---------------------------------------------------------------------------
// DifferentiableModalPlate, round 3.
// disp[t] = sum_m coef_m * exp(-sigma_m (t-1) K) * sin(t*omega_m*K), normalized.
//
// Synth strategy: per mode, seed (sin, cos, env) once with mod-2pi reduction +
// MUFU sin/cos/ex2, then produce 4 consecutive samples with 1-step rotations
// (s' = s*c1 + c*s1, c' = c*c1 - s*s1, env' = env*e1).  ~7.7 instrs/sample.
// Error budget analysis: phase deviation from the reference's fp32 rounding is
// bounded by t*w*K*1.2e-7*exp(-sigma*t*K) <= 2.7e-5 * coef (omega-sigma
// coupling), MUFU sin error 3.6e-7, rotation drift over 3 steps ~1e-6.
// ---------------------------------------------------------------------------

#define TPB     256
#define NCHUNK  160
#define CHUNK   40        // NCHUNK*CHUNK == MODES
#define MODES   6400
#define MMAXI   80
#define SPT     4         // samples per thread
#define TROW    22528     // padded partial-row length (mult of 4, >= 22527+1)

__device__ float4   g_modesA[MODES];        // {omega*K, -sigma*K*log2e, coef, exp(-sigma*K)}
__device__ float2   g_modesB[MODES];        // {sin(omega*K), cos(omega*K)}
__device__ float    g_part[NCHUNK][TROW];   // per-chunk partial time series
__device__ float    g_disp[TROW];           // combined output (unnormalized)
__device__ unsigned g_peak_bits;            // max |disp| as ordered uint bits

__device__ __forceinline__ float ex2a(float x) {
    float y; asm("ex2.approx.f32 %0, %1;" : "=f"(y) : "f"(x)); return y;
}

__device__ __forceinline__ float softplus_ref(float x) {
    return fmaxf(x, 0.0f) + log1pf(expf(-fabsf(x)));
}
__device__ __forceinline__ float sigmoid_ref(float x) {
    if (x >= 0.0f) { float e = expf(-x); return 1.0f / (1.0f + e); }
    float e = expf(x); return e / (1.0f + e);
}

// ---------------- per-mode parameter precompute (6400 threads) --------------
__global__ void plate_prep_kernel(const float* mu_raw, const float* Dmu_raw,
                                  const float* T0mu_raw, const float* Ly_raw,
                                  const float* xo_raw, const float* yo_raw)
{
    const float K_F   = (float)(1.0 / 44100.0);
    const float KK_F  = (float)((1.0 / 44100.0) * (1.0 / 44100.0));
    const float PI_F  = (float)M_PI;
    const float XIPI  = (float)((0.1 * 0.5) * M_PI);
    const float MAXOM = (float)(10000.0 * 2.0 * M_PI);
    const float MINOM = (float)(20.0 * 2.0 * M_PI);
    const double OM2SQ_D = (2.0 * M_PI * 500.0) * (2.0 * M_PI * 500.0);
    const float ALPHA_F = (float)(3.0 * log(10.0) / OM2SQ_D * (OM2SQ_D / 6.0));
    const float BETA_F  = (float)(3.0 * log(10.0) / OM2SQ_D * (1.0 / 1.0 - 1.0 / 6.0));

    int i = blockIdx.x * blockDim.x + threadIdx.x;
    if (i == 0) g_peak_bits = 0u;
    if (i >= MODES) return;

    float mu  = __fmul_rn(__fadd_rn(softplus_ref(*mu_raw),   1e-4f), 2.43f);
    float Dm  = __fmul_rn(__fadd_rn(softplus_ref(*Dmu_raw),  1e-4f), 0.002452f);
    float T0m = __fmul_rn(__fadd_rn(softplus_ref(*T0mu_raw), 1e-4f), 0.004115f);
    float Ly  = __fadd_rn(1.1f, __fmul_rn((float)(4.0 - 1.1), sigmoid_ref(*Ly_raw)));
    float xo  = __fadd_rn((float)(0.49 * 0.5),
                          __fmul_rn((float)((1.0 - 0.49) * 0.5), sigmoid_ref(*xo_raw)));
    float yo  = __fadd_rn(__fmul_rn(0.51f, Ly),
                          __fmul_rn(__fmul_rn((float)(1.0 - 0.51), Ly), sigmoid_ref(*yo_raw)));
    float yi  = __fmul_rn(0.1f, Ly);
    float ms  = __fmul_rn(__fmul_rn(__fmul_rn(0.25f, mu), 0.5f), Ly);

    float mf = (float)(i / MMAXI + 1);
    float nf = (float)(i % MMAXI + 1);
    float a = __fdiv_rn(__fmul_rn(mf, PI_F), 0.5f);
    float b = __fdiv_rn(__fmul_rn(nf, PI_F), Ly);
    float g1 = __fadd_rn(__fmul_rn(a, a), __fmul_rn(b, b));
    float osq = __fadd_rn(__fmul_rn(T0m, g1), __fmul_rn(__fmul_rn(Dm, g1), g1));
    float omega = sqrtf(fmaxf(osq, 0.0f));
    float valid = (omega <= MAXOM && omega >= MINOM) ? 1.0f : 0.0f;

    float InW = __fmul_rn(
        cosf(__fdiv_rn(__fmul_rn(XIPI, mf), 0.5f)),
        cosf(__fdiv_rn(__fmul_rn(__fmul_rn(yi, PI_F), nf), Ly)));
    float OutW = __fmul_rn(
        cosf(__fdiv_rn(__fmul_rn(__fmul_rn(xo, PI_F), mf), 0.5f)),
        cosf(__fdiv_rn(__fmul_rn(__fmul_rn(yo, PI_F), nf), Ly)));

    float sigma = __fadd_rn(ALPHA_F, __fmul_rn(BETA_F, __fmul_rn(omega, omega)));
    float e0 = expf(__fmul_rn(-sigma, K_F));
    float P = __fmul_rn(
        __fdiv_rn(__fmul_rn(__fmul_rn(__fmul_rn(OutW, InW), KK_F), e0), ms), valid);

    float w1   = __fmul_rn(omega, K_F);              // phase step (rad/sample)
    float den  = __fadd_rn(sinf(w1), 1e-8f);
    float coef = __fdiv_rn(P, den);
    float sigK = __fmul_rn(sigma, K_F);

    g_modesA[i] = make_float4(w1, -sigK * 1.4426950408889634f, coef, expf(-sigK));
    g_modesB[i] = make_float2(sinf(w1), cosf(w1));
}

// ---------------- main synthesis ------------------------------------------
__global__ void __launch_bounds__(TPB) plate_synth_kernel()
{
    const float TWOOPI = 0.63661977236758134f;
    const float TPI_HI = 6.283185482025146484375f;   // fl32(2*pi)
    const float TPI_LO = -1.7484555e-7f;             // 2*pi - TPI_HI

    __shared__ float4 smA[CHUNK];
    __shared__ float2 smB[CHUNK];
    int base = blockIdx.y * CHUNK;
    for (int j = threadIdx.x; j < CHUNK; j += TPB) {
        smA[j] = g_modesA[base + j];
        smB[j] = g_modesB[base + j];
    }
    __syncthreads();

    int gid = blockIdx.x * TPB + threadIdx.x;
    int t0 = gid * SPT;
    float t0f  = (float)t0;
    float tm1f = t0f - 1.0f;
    float acc0 = 0.0f, acc1 = 0.0f, acc2 = 0.0f, acc3 = 0.0f;

    #pragma unroll 2
    for (int j = 0; j < CHUNK; ++j) {
        float4 md = smA[j];
        float2 rb = smB[j];
        float s1 = rb.x, c1 = rb.y, e1 = md.w;

        // seed sample t0: mod-2pi reduce, MUFU sin/cos/ex2
        float ph = t0f * md.x;
        float z  = ph * TWOOPI;
        float qf = rintf(z);
        float r  = fmaf(qf, -TPI_HI, ph);
        r        = fmaf(qf, -TPI_LO, r);
        float s  = __sinf(r);
        float c  = __cosf(r);
        float e  = ex2a(tm1f * md.y) * md.z;       // coef * exp(-sigma*(t0-1)*K)
        acc0 = fmaf(e, s, acc0);

        // t0+1
        float s2 = fmaf(s, c1, c * s1);
        float c2 = fmaf(c, c1, -(s * s1));
        float e2 = e * e1;
        acc1 = fmaf(e2, s2, acc1);
        // t0+2
        float s3 = fmaf(s2, c1, c2 * s1);
        float c3 = fmaf(c2, c1, -(s2 * s1));
        float e3 = e2 * e1;
        acc2 = fmaf(e3, s3, acc2);
        // t0+3 (sine only)
        float s4 = fmaf(s3, c1, c3 * s1);
        float e4 = e3 * e1;
        acc3 = fmaf(e4, s4, acc3);
    }

    if (t0 + 3 < TROW) {
        float4 o = make_float4(acc0, acc1, acc2, acc3);
        *reinterpret_cast<float4*>(&g_part[blockIdx.y][t0]) = o;
    }
}

// ---------------- combine (fixed order) + peak via atomicMax ---------------
__global__ void plate_combine_kernel(int T)
{
    int t = blockIdx.x * TPB + threadIdx.x;
    float v = 0.0f;
    if (t < T) {
        #pragma unroll 8
        for (int c = 0; c < NCHUNK; ++c) v += g_part[c][t];
        g_disp[t] = v;
    }
    unsigned b = __float_as_uint(fabsf(v));
    b = __reduce_max_sync(0xffffffffu, b);
    __shared__ unsigned smx[TPB / 32];
    int w = threadIdx.x >> 5, l = threadIdx.x & 31;
    if (l == 0) smx[w] = b;
    __syncthreads();
    if (threadIdx.x == 0) {
        unsigned m = smx[0];
        #pragma unroll
        for (int i = 1; i < TPB / 32; ++i) m = max(m, smx[i]);
        atomicMax(&g_peak_bits, m);
    }
}

// ---------------- normalize -------------------------------------------------
__global__ void plate_norm_kernel(float* __restrict__ out, int T)
{
    int t = blockIdx.x * TPB + threadIdx.x;
    if (t < T) {
        float peak = __uint_as_float(g_peak_bits);
        out[t] = __fdiv_rn(g_disp[t], __fadd_rn(peak, 1e-8f));
    }
}

// ---------------------------------------------------------------------------
extern "C" void kernel_launch(void* const* d_in, const int* in_sizes, int n_in,
                              void* d_out, int out_size)
{
    const float* mu_raw   = (const float*)d_in[0];
    const float* Dmu_raw  = (const float*)d_in[1];
    const float* T0mu_raw = (const float*)d_in[2];
    const float* Ly_raw   = (const float*)d_in[3];
    const float* xo_raw   = (const float*)d_in[4];
    const float* yo_raw   = (const float*)d_in[5];
    float* out = (float*)d_out;

    int T = out_size;
    if (T > TROW) T = TROW;

    plate_prep_kernel<<<(MODES + TPB - 1) / TPB, TPB>>>(
        mu_raw, Dmu_raw, T0mu_raw, Ly_raw, xo_raw, yo_raw);

    int ngroups = (T + SPT - 1) / SPT;
    int gblocks = (ngroups + TPB - 1) / TPB;
    dim3 grid(gblocks, NCHUNK);
    plate_synth_kernel<<<grid, TPB>>>();

    int tblocks = (T + TPB - 1) / TPB;
    plate_combine_kernel<<<tblocks, TPB>>>(T);
    plate_norm_kernel<<<tblocks, TPB>>>(out, T);
}

// round 5
// speedup vs baseline: 5.0783x; 1.4715x over previous
#include <cuda_runtime.h>
#include <math.h>

// ---------------------------------------------------------------------------
// DifferentiableModalPlate, round 4.
//   u_m(t) = coef_m * exp(-sigma_m (t-1) K) * sin(t * omega_m * K)
//   disp[t] = sum_m u_m(t);  out = disp / (max|disp| + 1e-8)
//
// Synth: per (thread = 32 consecutive samples, mode): seed u(t0-1), u(t0) with
// mod-2pi + MUFU sin + MUFU ex2; one forward + one backward scalar Chebyshev
// step builds the two packed seed pairs; then 15 packed (f32x2) steps of
//   U_{k+1} = A2*U_k + B2*U_{k-1}       (damped -> strictly stable)
// at 3 packed FMA-pipe ops per 2 samples. Prep is fused into the synth kernel;
// combine+peak+normalize are fused into one kernel with a grid-wide software
// barrier (88 resident blocks).
// ---------------------------------------------------------------------------

#define TPB_S   128
#define SPT     32
#define CHUNK   100
#define NCHUNK  64          // CHUNK*NCHUNK == MODES
#define MODES   6400
#define MMAXI   80
#define TROW    22528       // 704 * 32, >= 22050
#define NGROUP  (TROW / SPT)            // 704
#define XBLK    ((NGROUP + TPB_S - 1) / TPB_S)   // 6
#define TPB_C   256
#define CBLK    (TROW / TPB_C)          // 88

typedef unsigned long long u64t;

__device__ float    g_part[NCHUNK][TROW];
__device__ unsigned g_peak_bits;
__device__ unsigned g_counter;

// ---- packed f32x2 helpers (sm_100+ PTX) -----------------------------------
__device__ __forceinline__ u64t pack2(float lo, float hi) {
    u64t r; asm("mov.b64 %0, {%1, %2};" : "=l"(r) : "f"(lo), "f"(hi)); return r;
}
__device__ __forceinline__ float2 unpack2(u64t v) {
    float2 r; asm("mov.b64 {%0, %1}, %2;" : "=f"(r.x), "=f"(r.y) : "l"(v)); return r;
}
__device__ __forceinline__ u64t mul2(u64t a, u64t b) {
    u64t r; asm("mul.rn.f32x2 %0, %1, %2;" : "=l"(r) : "l"(a), "l"(b)); return r;
}
__device__ __forceinline__ u64t add2(u64t a, u64t b) {
    u64t r; asm("add.rn.f32x2 %0, %1, %2;" : "=l"(r) : "l"(a), "l"(b)); return r;
}
__device__ __forceinline__ u64t fma2(u64t a, u64t b, u64t c) {
    u64t r; asm("fma.rn.f32x2 %0, %1, %2, %3;" : "=l"(r) : "l"(a), "l"(b), "l"(c)); return r;
}
__device__ __forceinline__ float ex2a(float x) {
    float y; asm("ex2.approx.f32 %0, %1;" : "=f"(y) : "f"(x)); return y;
}

__device__ __forceinline__ float softplus_ref(float x) {
    return fmaxf(x, 0.0f) + log1pf(expf(-fabsf(x)));
}
__device__ __forceinline__ float sigmoid_ref(float x) {
    if (x >= 0.0f) { float e = expf(-x); return 1.0f / (1.0f + e); }
    float e = expf(x); return e / (1.0f + e);
}

// ---- per-mode parameter computation (runs inside synth blocks) -------------
// A = {w1, -sigK*log2e, coef, A1},  B = {A2, B2, B1, invB1}
__device__ void prep_mode(int i,
                          const float* mu_raw, const float* Dmu_raw,
                          const float* T0mu_raw, const float* Ly_raw,
                          const float* xo_raw, const float* yo_raw,
                          float4* outA, float4* outB)
{
    const float K_F   = (float)(1.0 / 44100.0);
    const float KK_F  = (float)((1.0 / 44100.0) * (1.0 / 44100.0));
    const float PI_F  = (float)M_PI;
    const float XIPI  = (float)((0.1 * 0.5) * M_PI);
    const float MAXOM = (float)(10000.0 * 2.0 * M_PI);
    const float MINOM = (float)(20.0 * 2.0 * M_PI);
    const double OM2SQ_D = (2.0 * M_PI * 500.0) * (2.0 * M_PI * 500.0);
    const float ALPHA_F = (float)(3.0 * log(10.0) / OM2SQ_D * (OM2SQ_D / 6.0));
    const float BETA_F  = (float)(3.0 * log(10.0) / OM2SQ_D * (1.0 / 1.0 - 1.0 / 6.0));

    float mu  = __fmul_rn(__fadd_rn(softplus_ref(*mu_raw),   1e-4f), 2.43f);
    float Dm  = __fmul_rn(__fadd_rn(softplus_ref(*Dmu_raw),  1e-4f), 0.002452f);
    float T0m = __fmul_rn(__fadd_rn(softplus_ref(*T0mu_raw), 1e-4f), 0.004115f);
    float Ly  = __fadd_rn(1.1f, __fmul_rn((float)(4.0 - 1.1), sigmoid_ref(*Ly_raw)));
    float xo  = __fadd_rn((float)(0.49 * 0.5),
                          __fmul_rn((float)((1.0 - 0.49) * 0.5), sigmoid_ref(*xo_raw)));
    float yo  = __fadd_rn(__fmul_rn(0.51f, Ly),
                          __fmul_rn(__fmul_rn((float)(1.0 - 0.51), Ly), sigmoid_ref(*yo_raw)));
    float yi  = __fmul_rn(0.1f, Ly);
    float ms  = __fmul_rn(__fmul_rn(__fmul_rn(0.25f, mu), 0.5f), Ly);

    float mf = (float)(i / MMAXI + 1);
    float nf = (float)(i % MMAXI + 1);
    float a = __fdiv_rn(__fmul_rn(mf, PI_F), 0.5f);
    float b = __fdiv_rn(__fmul_rn(nf, PI_F), Ly);
    float g1 = __fadd_rn(__fmul_rn(a, a), __fmul_rn(b, b));
    float osq = __fadd_rn(__fmul_rn(T0m, g1), __fmul_rn(__fmul_rn(Dm, g1), g1));
    float omega = sqrtf(fmaxf(osq, 0.0f));
    float valid = (omega <= MAXOM && omega >= MINOM) ? 1.0f : 0.0f;

    float InW = __fmul_rn(
        cosf(__fdiv_rn(__fmul_rn(XIPI, mf), 0.5f)),
        cosf(__fdiv_rn(__fmul_rn(__fmul_rn(yi, PI_F), nf), Ly)));
    float OutW = __fmul_rn(
        cosf(__fdiv_rn(__fmul_rn(__fmul_rn(xo, PI_F), mf), 0.5f)),
        cosf(__fdiv_rn(__fmul_rn(__fmul_rn(yo, PI_F), nf), Ly)));

    float sigma = __fadd_rn(ALPHA_F, __fmul_rn(BETA_F, __fmul_rn(omega, omega)));
    float e0 = expf(__fmul_rn(-sigma, K_F));
    float P = __fmul_rn(
        __fdiv_rn(__fmul_rn(__fmul_rn(__fmul_rn(OutW, InW), KK_F), e0), ms), valid);

    float w1   = __fmul_rn(omega, K_F);
    float s1   = sinf(w1);
    float c1   = cosf(w1);
    float c2w  = cosf(2.0f * w1);
    float den  = __fadd_rn(s1, 1e-8f);
    float coef = __fdiv_rn(P, den);
    float sigK = __fmul_rn(sigma, K_F);
    float e1   = expf(-sigK);
    float e2   = e1 * e1;

    float A1 = 2.0f * e1 * c1;
    float B1 = -e2;
    float invB1 = -1.0f / e2;
    float A2 = 2.0f * e2 * c2w;
    float B2 = -(e2 * e2);

    *outA = make_float4(w1, -sigK * 1.4426950408889634f, coef, A1);
    *outB = make_float4(A2, B2, B1, invB1);
}

// ---- main synthesis --------------------------------------------------------
__global__ void __launch_bounds__(TPB_S)
plate_synth_kernel(const float* mu_raw, const float* Dmu_raw,
                   const float* T0mu_raw, const float* Ly_raw,
                   const float* xo_raw, const float* yo_raw)
{
    const float TWOOPI = 0.63661977236758134f;
    const float TPI_HI = 6.283185482025146484375f;   // fl32(2*pi)
    const float TPI_LO = -1.7484555e-7f;             // 2*pi - TPI_HI

    __shared__ float4 smA[CHUNK];
    __shared__ float4 smB[CHUNK];

    if (blockIdx.x == 0 && blockIdx.y == 0 && threadIdx.x == 0) {
        g_peak_bits = 0u;       // reset reduction state for this launch
        g_counter   = 0u;
    }

    int base = blockIdx.y * CHUNK;
    if (threadIdx.x < CHUNK) {
        prep_mode(base + threadIdx.x, mu_raw, Dmu_raw, T0mu_raw,
                  Ly_raw, xo_raw, yo_raw,
                  &smA[threadIdx.x], &smB[threadIdx.x]);
    }
    __syncthreads();

    int g = blockIdx.x * TPB_S + threadIdx.x;
    if (g >= NGROUP) return;

    int   t0    = g * SPT;
    float t0f   = (float)t0;
    float t0m1f = t0f - 1.0f;
    float t0m2f = t0f - 2.0f;

    u64t acc[SPT / 2];
    #pragma unroll
    for (int k = 0; k < SPT / 2; ++k) acc[k] = 0ull;

    #pragma unroll 1
    for (int j = 0; j < CHUNK; ++j) {
        float4 A = smA[j];
        float4 B = smB[j];

        // seed u(t0): coef*exp(-sigma*(t0-1)K)*sin(t0*w)
        float ph = t0f * A.x;
        float z  = ph * TWOOPI;
        float q  = rintf(z);
        float r  = fmaf(q, -TPI_HI, ph);
        r        = fmaf(q, -TPI_LO, r);
        float u0 = (ex2a(t0m1f * A.y) * A.z) * __sinf(r);

        // seed u(t0-1)
        float phm = t0m1f * A.x;
        float zm  = phm * TWOOPI;
        float qm  = rintf(zm);
        float rm  = fmaf(qm, -TPI_HI, phm);
        rm        = fmaf(qm, -TPI_LO, rm);
        float um1 = (ex2a(t0m2f * A.y) * A.z) * __sinf(rm);

        // forward + backward scalar Chebyshev steps (Delta = 1)
        float u1  = fmaf(A.w, u0, B.z * um1);          // A1*u0 + B1*u(-1)
        float um2 = fmaf(-A.w, um1, u0) * B.w;         // (u0 - A1*u(-1)) * invB1

        u64t A2v   = pack2(B.x, B.x);
        u64t B2v   = pack2(B.y, B.y);
        u64t Ucur  = pack2(u0, u1);
        u64t Uprev = pack2(um2, um1);

        acc[0] = add2(acc[0], Ucur);
        #pragma unroll
        for (int k = 1; k < SPT / 2; ++k) {
            u64t tmp = mul2(B2v, Uprev);
            u64t Un  = fma2(A2v, Ucur, tmp);
            acc[k] = add2(acc[k], Un);
            Uprev = Ucur;
            Ucur  = Un;
        }
    }

    float4* dst = reinterpret_cast<float4*>(&g_part[blockIdx.y][t0]);
    #pragma unroll
    for (int k = 0; k < SPT / 2; k += 2) {
        float2 p = unpack2(acc[k]);
        float2 qq = unpack2(acc[k + 1]);
        dst[k / 2] = make_float4(p.x, p.y, qq.x, qq.y);
    }
}

// ---- combine + peak + normalize (grid-wide software barrier) ---------------
__global__ void __launch_bounds__(TPB_C)
plate_finish_kernel(float* __restrict__ out, int T)
{
    int t = blockIdx.x * TPB_C + threadIdx.x;

    float v = 0.0f;
    #pragma unroll 8
    for (int c = 0; c < NCHUNK; ++c) v += g_part[c][t];

    float av = (t < T) ? fabsf(v) : 0.0f;
    unsigned b = __float_as_uint(av);
    b = __reduce_max_sync(0xffffffffu, b);

    __shared__ unsigned smx[TPB_C / 32];
    int w = threadIdx.x >> 5, l = threadIdx.x & 31;
    if (l == 0) smx[w] = b;
    __syncthreads();
    if (threadIdx.x == 0) {
        unsigned m = smx[0];
        #pragma unroll
        for (int i = 1; i < TPB_C / 32; ++i) m = max(m, smx[i]);
        atomicMax(&g_peak_bits, m);
        __threadfence();
        atomicAdd(&g_counter, 1u);
        // spin until all blocks have published their block max
        while (*((volatile unsigned*)&g_counter) < (unsigned)CBLK) { }
    }
    __syncthreads();

    float peak = __uint_as_float(*((volatile unsigned*)&g_peak_bits));
    if (t < T)
        out[t] = __fdiv_rn(v, __fadd_rn(peak, 1e-8f));
}

// ---------------------------------------------------------------------------
extern "C" void kernel_launch(void* const* d_in, const int* in_sizes, int n_in,
                              void* d_out, int out_size)
{
    const float* mu_raw   = (const float*)d_in[0];
    const float* Dmu_raw  = (const float*)d_in[1];
    const float* T0mu_raw = (const float*)d_in[2];
    const float* Ly_raw   = (const float*)d_in[3];
    const float* xo_raw   = (const float*)d_in[4];
    const float* yo_raw   = (const float*)d_in[5];
    float* out = (float*)d_out;

    int T = out_size;
    if (T > TROW) T = TROW;

    dim3 grid(XBLK, NCHUNK);
    plate_synth_kernel<<<grid, TPB_S>>>(mu_raw, Dmu_raw, T0mu_raw,
                                        Ly_raw, xo_raw, yo_raw);
    plate_finish_kernel<<<CBLK, TPB_C>>>(out, T);
}